// round 13
// baseline (speedup 1.0000x reference)
#include <cuda_runtime.h>
#include <cstdint>
#include <cub/block/block_radix_sort.cuh>

typedef unsigned int u32;
typedef unsigned short u16;

#define BB 8
#define NN 16384
#define DD 64
#define NCMAX 512
#define EPSF 0.1f
#define NROWS (BB*DD)

#define SBT 1024
#define SIPT 16

#define LTPB 512
#define LPT 32
#define LWARPS 16

__device__ float g_featT[(size_t)BB*DD*NN];   // (b, d, n) transposed features
__device__ u32   g_sorted[(size_t)BB*DD*NN];  // per-row sorted (monotone u32) keys
__device__ u16   g_sidx[(size_t)BB*DD*NN];    // original index per sorted position
__device__ short g_lab[(size_t)BB*DD*NN];     // per-point local labels
__device__ int   g_ncl[NROWS];

__device__ __forceinline__ u32 f2u(float f){
    u32 u = __float_as_uint(f);
    return (u & 0x80000000u) ? ~u : (u | 0x80000000u);
}
__device__ __forceinline__ float u2f(u32 u){
    u32 v = (u & 0x80000000u) ? (u & 0x7fffffffu) : ~u;
    return __uint_as_float(v);
}
__device__ __forceinline__ float posInf(){ return __int_as_float(0x7f800000); }
__device__ __forceinline__ float negInf(){ return __int_as_float((int)0xff800000); }

// XOR bank swizzle: bijective (high bits unchanged). With LPT=32 the
// per-thread pattern i=tid*32+e maps to bank = e ^ lane -> conflict-free.
__device__ __forceinline__ int sidx(int i){ return i ^ ((i >> 5) & 31); }

// ---------------- warp scans ----------------
__device__ __forceinline__ u32 warpInclAdd(u32 v){
    int lane = threadIdx.x & 31;
    #pragma unroll
    for (int o = 1; o < 32; o <<= 1){
        u32 t = __shfl_up_sync(0xffffffffu, v, o);
        if (lane >= o) v += t;
    }
    return v;
}
__device__ __forceinline__ int warpInclMax(int v){
    int lane = threadIdx.x & 31;
    #pragma unroll
    for (int o = 1; o < 32; o <<= 1){
        int t = __shfl_up_sync(0xffffffffu, v, o);
        if (lane >= o) v = max(v, t);
    }
    return v;
}
__device__ __forceinline__ int warpInclMin(int v){
    int lane = threadIdx.x & 31;
    #pragma unroll
    for (int o = 1; o < 32; o <<= 1){
        int t = __shfl_up_sync(0xffffffffu, v, o);
        if (lane >= o) v = min(v, t);
    }
    return v;
}

// ---------------- block scans (LTPB threads, all must call) ----------------
__device__ u32 blkExclAdd(u32 v, int* tmp, u32* total){
    int lane = threadIdx.x & 31, w = threadIdx.x >> 5;
    u32 inc = warpInclAdd(v);
    if (lane == 31) tmp[w] = (int)inc;
    __syncthreads();
    if (w == 0){
        u32 t = (lane < LWARPS) ? (u32)tmp[lane] : 0u;
        u32 ti = warpInclAdd(t);
        if (lane < LWARPS) tmp[lane] = (int)ti;
    }
    __syncthreads();
    u32 carry = (w > 0) ? (u32)tmp[w-1] : 0u;
    if (total) *total = (u32)tmp[LWARPS-1];
    u32 res = carry + inc - v;
    __syncthreads();
    return res;
}
__device__ int blkExclMax(int v, int* tmp){   // identity -1
    int lane = threadIdx.x & 31, w = threadIdx.x >> 5;
    int inc = warpInclMax(v);
    int ex = __shfl_up_sync(0xffffffffu, inc, 1);
    if (lane == 0) ex = -1;
    if (lane == 31) tmp[w] = inc;
    __syncthreads();
    if (w == 0){
        int t = (lane < LWARPS) ? tmp[lane] : -1;
        int ti = warpInclMax(t);
        if (lane < LWARPS) tmp[lane] = ti;
    }
    __syncthreads();
    int carry = (w > 0) ? tmp[w-1] : -1;
    int res = max(carry, ex);
    __syncthreads();
    return res;
}
__device__ int blkExclMin(int v, int* tmp){   // identity NN
    int lane = threadIdx.x & 31, w = threadIdx.x >> 5;
    int inc = warpInclMin(v);
    int ex = __shfl_up_sync(0xffffffffu, inc, 1);
    if (lane == 0) ex = NN;
    if (lane == 31) tmp[w] = inc;
    __syncthreads();
    if (w == 0){
        int t = (lane < LWARPS) ? tmp[lane] : NN;
        int ti = warpInclMin(t);
        if (lane < LWARPS) tmp[lane] = ti;
    }
    __syncthreads();
    int carry = (w > 0) ? tmp[w-1] : NN;
    int res = min(carry, ex);
    __syncthreads();
    return res;
}
// reverse exclusive min: for thread t, min over threads t' > t
__device__ int blkRevExclMin(int v, int* tmp, int* xch){
    int t = threadIdx.x;
    xch[(LTPB-1) - t] = v; __syncthreads();
    int rv = xch[t];        __syncthreads();
    int e = blkExclMin(rv, tmp);
    xch[t] = e;             __syncthreads();
    int r = xch[(LTPB-1) - t]; __syncthreads();
    return r;
}

// ---------------- no-op kernel (ncu slot aiming) ----------------
__global__ void noop_kernel(){}

// ---------------- transpose: (B,N,D) -> (B,D,N) ----------------
__global__ void transpose_kernel(const float* __restrict__ feat){
    __shared__ float tile[32][33];
    int b  = blockIdx.z;
    int d0 = blockIdx.y * 32;
    int n0 = blockIdx.x * 32;
    int tx = threadIdx.x, ty = threadIdx.y;
    tile[ty][tx] = feat[((size_t)b*NN + (n0+ty))*DD + (d0+tx)];
    __syncthreads();
    g_featT[((size_t)b*DD + (d0+ty))*NN + (n0+tx)] = tile[tx][ty];
}

// ---------------- sort: CUB pair radix sort, 1024 thr x 16 items ----------
// 16 items/thread halves register state vs 32 -> no RF-occupancy cliff
// (512x32 config needed 128 regs = whole RF = hard 1 CTA with 16 warps).
typedef cub::BlockRadixSort<u32, SBT, SIPT, u16, 6> BlockSort;

__global__ void __launch_bounds__(SBT) sort_kernel(){
    extern __shared__ char smemRaw[];
    typename BlockSort::TempStorage* ts =
        reinterpret_cast<typename BlockSort::TempStorage*>(smemRaw);
    int row = blockIdx.x;
    const float* __restrict__ xrow = g_featT + (size_t)row * NN;
    int t = threadIdx.x;
    u32 keys[SIPT];
    u16 vals[SIPT];
    #pragma unroll
    for (int j = 0; j < SIPT; ++j){
        int src = j*SBT + t;            // striped load; pairing is what matters
        keys[j] = f2u(xrow[src]);
        vals[j] = (u16)src;
    }
    BlockSort(*ts).SortBlockedToStriped(keys, vals);
    u32* __restrict__ srow = g_sorted + (size_t)row * NN;
    u16* __restrict__ irow = g_sidx   + (size_t)row * NN;
    #pragma unroll
    for (int j = 0; j < SIPT; ++j){
        srow[j*SBT + t] = keys[j];
        irow[j*SBT + t] = vals[j];
    }
}

// ---------------- label kernel: one block per row, 2 CTAs/SM ---------------
struct LSmem {
    float xs[NN];        // sorted values, swizzled storage (64KB)
    short cidS[NN];      // cid / ni-temp / final labels, swizzled storage (32KB)
    int xch[LTPB];
    int tmp[LWARPS+1];
};

__global__ void __launch_bounds__(LTPB, 2) label_kernel(){
    extern __shared__ char smemRaw[];
    LSmem* S = reinterpret_cast<LSmem*>(smemRaw);
    int row = blockIdx.x;
    const u32* __restrict__ srow = g_sorted + (size_t)row * NN;
    const u16* __restrict__ irow = g_sidx   + (size_t)row * NN;
    int tid = threadIdx.x;

    float* xs = S->xs;
    for (int i = tid; i < NN; i += LTPB) xs[sidx(i)] = u2f(srow[i]);
    __syncthreads();

    // bounds-checked sorted-value load (sentinels outside [0,NN))
    auto loadx = [&](int i) -> float {
        if (i < 0)   return negInf();
        if (i >= NN) return posInf();
        return xs[sidx(i)];
    };

    // ---- core test, O(1) per element via 9-point sliding window ----
    // core(i)  <=>  exists k in [0,4]: xs[i-k] >= x-eps  AND  xs[i+4-k] <= x+eps
    int p0 = tid * LPT;
    u32 coreMask = 0;
    {
        float v[9];
        #pragma unroll
        for (int j = 0; j < 9; ++j) v[j] = loadx(p0 - 4 + j);
        #pragma unroll
        for (int e = 0; e < LPT; ++e){
            float x = v[4];
            float a = x + EPSF, bnd = x - EPSF;
            bool core = false;
            #pragma unroll
            for (int k = 0; k <= 4; ++k)
                core |= (v[4 - k] >= bnd) && (v[8 - k] <= a);
            if (core) coreMask |= (1u << e);
            #pragma unroll
            for (int j = 0; j < 8; ++j) v[j] = v[j + 1];
            v[8] = loadx(p0 + e + 5);
        }
    }

    // per-thread summaries
    int localPrev = -1, localNext = NN;
    #pragma unroll
    for (int e = 0; e < LPT; ++e) if (coreMask & (1u << e)) localPrev = p0 + e;
    #pragma unroll
    for (int e = LPT-1; e >= 0; --e) if (coreMask & (1u << e)) localNext = p0 + e;

    int carryP = blkExclMax(localPrev, S->tmp);
    int carryN = blkRevExclMin(localNext, S->tmp, S->xch);

    // new-cluster flags + local count
    u32 ncMask = 0;
    {
        int runP = carryP;
        #pragma unroll
        for (int e = 0; e < LPT; ++e){
            if (coreMask & (1u << e)){
                float x = xs[sidx(p0 + e)];
                float pv = (runP >= 0) ? xs[sidx(runP)] : negInf();
                if (x - pv > EPSF) ncMask |= (1u << e);
                runP = p0 + e;
            }
        }
    }
    u32 total = 0;
    u32 carryC = blkExclAdd((u32)__popc(ncMask), S->tmp, &total);

    // cid per sorted position (swizzled short layout)
    short* cid = S->cidS;
    {
        int c = (int)carryC;
        #pragma unroll
        for (int e = 0; e < LPT; ++e){
            if (ncMask & (1u << e)) ++c;
            cid[sidx(p0 + e)] = (short)(c - 1);
        }
    }
    __syncthreads();

    // labels in place: reverse pass stashes next-core index in BORDER slots;
    // forward pass reads cross-thread data only from CORE slots.
    {
        int rN = carryN;
        #pragma unroll
        for (int e = LPT-1; e >= 0; --e){
            int idx = p0 + e;
            if (coreMask & (1u << e)) rN = idx;
            else cid[sidx(idx)] = (short)rN;
        }
        int rP = carryP;
        #pragma unroll
        for (int e = 0; e < LPT; ++e){
            int idx = p0 + e;
            if (coreMask & (1u << e)){
                rP = idx;
            } else {
                int ni = cid[sidx(idx)];
                float x = xs[sidx(idx)];
                float lv = (rP >= 0) ? xs[sidx(rP)]  : negInf();
                float rv = (ni < NN) ? xs[sidx(ni)]  : posInf();
                float dl = x - lv, dr = rv - x;
                int lc = (rP >= 0) ? cid[sidx(rP)] : -1;
                int rc = (ni < NN) ? cid[sidx(ni)] : -1;
                int bc = (dl <= dr) ? lc : rc;
                int l = (fminf(dl, dr) <= EPSF) ? bc : -1;
                cid[sidx(idx)] = (short)l;
            }
        }
    }
    __syncthreads();

    // scatter: label of sorted position i goes to original index irow[i]
    short* glabRow = g_lab + (size_t)row * NN;
    for (int i = tid; i < NN; i += LTPB){
        glabRow[irow[i]] = cid[sidx(i)];
    }
    if (tid == 0) g_ncl[row] = (int)total;
}

// ---------------- output: offsets computed per-block + bitmap expansion ----
__global__ void __launch_bounds__(256) output_kernel(float* __restrict__ out){
    __shared__ short labT[DD][66];
    __shared__ int offs[DD];
    int b  = blockIdx.y;
    int n0 = blockIdx.x * 64;
    int tid = threadIdx.x, w = tid >> 5, lane = tid & 31;

    // per-block exclusive prefix over g_ncl (64 dims, trivial)
    int myv = 0;
    if (tid < DD){ myv = g_ncl[b*DD + tid]; offs[tid] = myv; }
    __syncthreads();
    #pragma unroll
    for (int o = 1; o < DD; o <<= 1){
        int t2 = 0;
        if (tid < DD && tid >= o) t2 = offs[tid - o];
        __syncthreads();
        if (tid < DD) offs[tid] += t2;
        __syncthreads();
    }
    if (tid < DD) offs[tid] -= myv;   // exclusive

    for (int l = tid; l < DD*64; l += 256){
        int d = l >> 6, i = l & 63;
        labT[d][i] = g_lab[((size_t)(b*DD + d))*NN + n0 + i];
    }
    __syncthreads();

    int q = lane >> 3;
    for (int i = w; i < 64; i += 8){
        int lb0 = labT[lane][i];
        int lb1 = labT[lane + 32][i];
        int g0 = -1, g1 = -1;
        if (lb0 >= 0){ int g = lb0 + offs[lane];      if (g < NCMAX) g0 = g; }
        if (lb1 >= 0){ int g = lb1 + offs[lane + 32]; if (g < NCMAX) g1 = g; }
        u32 myw[4];
        #pragma unroll
        for (int wi = 0; wi < 16; ++wi){
            u32 c = 0;
            if ((g0 >> 5) == wi) c |= 1u << (g0 & 31);
            if ((g1 >> 5) == wi) c |= 1u << (g1 & 31);
            u32 word = __reduce_or_sync(0xffffffffu, c);
            if (q == (wi & 3)) myw[wi >> 2] = word;
        }
        float4* op = reinterpret_cast<float4*>(out + ((size_t)(b*NN + n0 + i))*NCMAX);
        int sh = (lane & 7) * 4;
        #pragma unroll
        for (int k = 0; k < 4; ++k){
            u32 word = myw[k];
            float4 v;
            v.x = (word >> (sh + 0)) & 1u ? 1.0f : 0.0f;
            v.y = (word >> (sh + 1)) & 1u ? 1.0f : 0.0f;
            v.z = (word >> (sh + 2)) & 1u ? 1.0f : 0.0f;
            v.w = (word >> (sh + 3)) & 1u ? 1.0f : 0.0f;
            __stcs(op + k*32 + lane, v);
        }
    }
}

extern "C" void kernel_launch(void* const* d_in, const int* in_sizes, int n_in,
                              void* d_out, int out_size){
    const float* feat = (const float*)d_in[0];
    float* out = (float*)d_out;
    (void)in_sizes; (void)n_in; (void)out_size;

    int sortSmem = (int)sizeof(typename BlockSort::TempStorage);
    cudaFuncSetAttribute(sort_kernel,
                         cudaFuncAttributeMaxDynamicSharedMemorySize, sortSmem);
    cudaFuncSetAttribute(label_kernel,
                         cudaFuncAttributeMaxDynamicSharedMemorySize,
                         (int)sizeof(LSmem));

    transpose_kernel<<<dim3(NN/32, DD/32, BB), dim3(32, 32)>>>(feat);   // #1
    noop_kernel<<<1, 32>>>();                                           // #2
    noop_kernel<<<1, 32>>>();                                           // #3
    sort_kernel<<<NROWS, SBT, sortSmem>>>();                            // #4 (ncu slot)
    label_kernel<<<NROWS, LTPB, sizeof(LSmem)>>>();                     // #5
    output_kernel<<<dim3(NN/64, BB), 256>>>(out);                       // #6
}

// round 14
// speedup vs baseline: 1.1750x; 1.1750x over previous
#include <cuda_runtime.h>
#include <cstdint>
#include <cub/block/block_radix_sort.cuh>

typedef unsigned int u32;
typedef unsigned short u16;

#define BB 8
#define NN 16384
#define DD 64
#define NCMAX 512
#define EPSF 0.1f
#define NROWS (BB*DD)

#define SBT 512
#define SIPT 32

#define LTPB 512
#define LPT 32
#define LWARPS 16

__device__ float g_featT[(size_t)BB*DD*NN];   // (b, d, n) transposed features
__device__ u32   g_sorted[(size_t)BB*DD*NN];  // per-row sorted (monotone u32) keys
__device__ u16   g_sidx[(size_t)BB*DD*NN];    // original index per sorted position
__device__ short g_lab[(size_t)BB*DD*NN];     // per-point local labels
__device__ int   g_ncl[NROWS];

__device__ __forceinline__ u32 f2u(float f){
    u32 u = __float_as_uint(f);
    return (u & 0x80000000u) ? ~u : (u | 0x80000000u);
}
__device__ __forceinline__ float u2f(u32 u){
    u32 v = (u & 0x80000000u) ? (u & 0x7fffffffu) : ~u;
    return __uint_as_float(v);
}
__device__ __forceinline__ float posInf(){ return __int_as_float(0x7f800000); }
__device__ __forceinline__ float negInf(){ return __int_as_float((int)0xff800000); }

// XOR bank swizzle: bijective (high bits unchanged). With LPT=32 the
// per-thread pattern i=tid*32+e maps to bank = e ^ lane -> conflict-free.
__device__ __forceinline__ int sidx(int i){ return i ^ ((i >> 5) & 31); }

// ---------------- warp scans ----------------
__device__ __forceinline__ u32 warpInclAdd(u32 v){
    int lane = threadIdx.x & 31;
    #pragma unroll
    for (int o = 1; o < 32; o <<= 1){
        u32 t = __shfl_up_sync(0xffffffffu, v, o);
        if (lane >= o) v += t;
    }
    return v;
}
__device__ __forceinline__ int warpInclMax(int v){
    int lane = threadIdx.x & 31;
    #pragma unroll
    for (int o = 1; o < 32; o <<= 1){
        int t = __shfl_up_sync(0xffffffffu, v, o);
        if (lane >= o) v = max(v, t);
    }
    return v;
}
__device__ __forceinline__ int warpInclMin(int v){
    int lane = threadIdx.x & 31;
    #pragma unroll
    for (int o = 1; o < 32; o <<= 1){
        int t = __shfl_up_sync(0xffffffffu, v, o);
        if (lane >= o) v = min(v, t);
    }
    return v;
}

// ---------------- block scans (LTPB threads, all must call) ----------------
__device__ u32 blkExclAdd(u32 v, int* tmp, u32* total){
    int lane = threadIdx.x & 31, w = threadIdx.x >> 5;
    u32 inc = warpInclAdd(v);
    if (lane == 31) tmp[w] = (int)inc;
    __syncthreads();
    if (w == 0){
        u32 t = (lane < LWARPS) ? (u32)tmp[lane] : 0u;
        u32 ti = warpInclAdd(t);
        if (lane < LWARPS) tmp[lane] = (int)ti;
    }
    __syncthreads();
    u32 carry = (w > 0) ? (u32)tmp[w-1] : 0u;
    if (total) *total = (u32)tmp[LWARPS-1];
    u32 res = carry + inc - v;
    __syncthreads();
    return res;
}
__device__ int blkExclMax(int v, int* tmp){   // identity -1
    int lane = threadIdx.x & 31, w = threadIdx.x >> 5;
    int inc = warpInclMax(v);
    int ex = __shfl_up_sync(0xffffffffu, inc, 1);
    if (lane == 0) ex = -1;
    if (lane == 31) tmp[w] = inc;
    __syncthreads();
    if (w == 0){
        int t = (lane < LWARPS) ? tmp[lane] : -1;
        int ti = warpInclMax(t);
        if (lane < LWARPS) tmp[lane] = ti;
    }
    __syncthreads();
    int carry = (w > 0) ? tmp[w-1] : -1;
    int res = max(carry, ex);
    __syncthreads();
    return res;
}
__device__ int blkExclMin(int v, int* tmp){   // identity NN
    int lane = threadIdx.x & 31, w = threadIdx.x >> 5;
    int inc = warpInclMin(v);
    int ex = __shfl_up_sync(0xffffffffu, inc, 1);
    if (lane == 0) ex = NN;
    if (lane == 31) tmp[w] = inc;
    __syncthreads();
    if (w == 0){
        int t = (lane < LWARPS) ? tmp[lane] : NN;
        int ti = warpInclMin(t);
        if (lane < LWARPS) tmp[lane] = ti;
    }
    __syncthreads();
    int carry = (w > 0) ? tmp[w-1] : NN;
    int res = min(carry, ex);
    __syncthreads();
    return res;
}
// reverse exclusive min: for thread t, min over threads t' > t
__device__ int blkRevExclMin(int v, int* tmp, int* xch){
    int t = threadIdx.x;
    xch[(LTPB-1) - t] = v; __syncthreads();
    int rv = xch[t];        __syncthreads();
    int e = blkExclMin(rv, tmp);
    xch[t] = e;             __syncthreads();
    int r = xch[(LTPB-1) - t]; __syncthreads();
    return r;
}

// ---------------- no-op kernel (ncu slot aiming) ----------------
__global__ void noop_kernel(){}

// ---------------- transpose: (B,N,D) -> (B,D,N) ----------------
__global__ void transpose_kernel(const float* __restrict__ feat){
    __shared__ float tile[32][33];
    int b  = blockIdx.z;
    int d0 = blockIdx.y * 32;
    int n0 = blockIdx.x * 32;
    int tx = threadIdx.x, ty = threadIdx.y;
    tile[ty][tx] = feat[((size_t)b*NN + (n0+ty))*DD + (d0+tx)];
    __syncthreads();
    g_featT[((size_t)b*DD + (d0+ty))*NN + (n0+tx)] = tile[tx][ty];
}

// ---------------- sort: CUB pair radix sort, 512 thr x 32 items, 7-bit ----
// 512x32 is the proven non-spilling shape (128 regs, no LDL/STL).
// RADIX_BITS=7 -> ceil(32/7)=5 passes instead of 6. Rank counters grow to
// ~128KB smem but the kernel is RF-bound at 1 CTA/SM anyway -> free.
typedef cub::BlockRadixSort<u32, SBT, SIPT, u16, 7> BlockSort;

__global__ void __launch_bounds__(SBT) sort_kernel(){
    extern __shared__ char smemRaw[];
    typename BlockSort::TempStorage* ts =
        reinterpret_cast<typename BlockSort::TempStorage*>(smemRaw);
    int row = blockIdx.x;
    const float* __restrict__ xrow = g_featT + (size_t)row * NN;
    int t = threadIdx.x;
    u32 keys[SIPT];
    u16 vals[SIPT];
    #pragma unroll
    for (int j = 0; j < SIPT; ++j){
        int src = j*SBT + t;            // striped load; pairing is what matters
        keys[j] = f2u(xrow[src]);
        vals[j] = (u16)src;
    }
    BlockSort(*ts).SortBlockedToStriped(keys, vals);
    u32* __restrict__ srow = g_sorted + (size_t)row * NN;
    u16* __restrict__ irow = g_sidx   + (size_t)row * NN;
    #pragma unroll
    for (int j = 0; j < SIPT; ++j){
        srow[j*SBT + t] = keys[j];
        irow[j*SBT + t] = vals[j];
    }
}

// ---------------- label kernel: one block per row, 2 CTAs/SM ---------------
struct LSmem {
    float xs[NN];        // sorted values, swizzled storage (64KB)
    short cidS[NN];      // cid / ni-temp / final labels, swizzled storage (32KB)
    int xch[LTPB];
    int tmp[LWARPS+1];
};

__global__ void __launch_bounds__(LTPB, 2) label_kernel(){
    extern __shared__ char smemRaw[];
    LSmem* S = reinterpret_cast<LSmem*>(smemRaw);
    int row = blockIdx.x;
    const u32* __restrict__ srow = g_sorted + (size_t)row * NN;
    const u16* __restrict__ irow = g_sidx   + (size_t)row * NN;
    int tid = threadIdx.x;

    float* xs = S->xs;
    for (int i = tid; i < NN; i += LTPB) xs[sidx(i)] = u2f(srow[i]);
    __syncthreads();

    // bounds-checked sorted-value load (sentinels outside [0,NN))
    auto loadx = [&](int i) -> float {
        if (i < 0)   return negInf();
        if (i >= NN) return posInf();
        return xs[sidx(i)];
    };

    // ---- core test, O(1) per element via 9-point sliding window ----
    // core(i)  <=>  exists k in [0,4]: xs[i-k] >= x-eps  AND  xs[i+4-k] <= x+eps
    int p0 = tid * LPT;
    u32 coreMask = 0;
    {
        float v[9];
        #pragma unroll
        for (int j = 0; j < 9; ++j) v[j] = loadx(p0 - 4 + j);
        #pragma unroll
        for (int e = 0; e < LPT; ++e){
            float x = v[4];
            float a = x + EPSF, bnd = x - EPSF;
            bool core = false;
            #pragma unroll
            for (int k = 0; k <= 4; ++k)
                core |= (v[4 - k] >= bnd) && (v[8 - k] <= a);
            if (core) coreMask |= (1u << e);
            #pragma unroll
            for (int j = 0; j < 8; ++j) v[j] = v[j + 1];
            v[8] = loadx(p0 + e + 5);
        }
    }

    // per-thread summaries
    int localPrev = -1, localNext = NN;
    #pragma unroll
    for (int e = 0; e < LPT; ++e) if (coreMask & (1u << e)) localPrev = p0 + e;
    #pragma unroll
    for (int e = LPT-1; e >= 0; --e) if (coreMask & (1u << e)) localNext = p0 + e;

    int carryP = blkExclMax(localPrev, S->tmp);
    int carryN = blkRevExclMin(localNext, S->tmp, S->xch);

    // new-cluster flags + local count
    u32 ncMask = 0;
    {
        int runP = carryP;
        #pragma unroll
        for (int e = 0; e < LPT; ++e){
            if (coreMask & (1u << e)){
                float x = xs[sidx(p0 + e)];
                float pv = (runP >= 0) ? xs[sidx(runP)] : negInf();
                if (x - pv > EPSF) ncMask |= (1u << e);
                runP = p0 + e;
            }
        }
    }
    u32 total = 0;
    u32 carryC = blkExclAdd((u32)__popc(ncMask), S->tmp, &total);

    // cid per sorted position (swizzled short layout)
    short* cid = S->cidS;
    {
        int c = (int)carryC;
        #pragma unroll
        for (int e = 0; e < LPT; ++e){
            if (ncMask & (1u << e)) ++c;
            cid[sidx(p0 + e)] = (short)(c - 1);
        }
    }
    __syncthreads();

    // labels in place: reverse pass stashes next-core index in BORDER slots;
    // forward pass reads cross-thread data only from CORE slots.
    {
        int rN = carryN;
        #pragma unroll
        for (int e = LPT-1; e >= 0; --e){
            int idx = p0 + e;
            if (coreMask & (1u << e)) rN = idx;
            else cid[sidx(idx)] = (short)rN;
        }
        int rP = carryP;
        #pragma unroll
        for (int e = 0; e < LPT; ++e){
            int idx = p0 + e;
            if (coreMask & (1u << e)){
                rP = idx;
            } else {
                int ni = cid[sidx(idx)];
                float x = xs[sidx(idx)];
                float lv = (rP >= 0) ? xs[sidx(rP)]  : negInf();
                float rv = (ni < NN) ? xs[sidx(ni)]  : posInf();
                float dl = x - lv, dr = rv - x;
                int lc = (rP >= 0) ? cid[sidx(rP)] : -1;
                int rc = (ni < NN) ? cid[sidx(ni)] : -1;
                int bc = (dl <= dr) ? lc : rc;
                int l = (fminf(dl, dr) <= EPSF) ? bc : -1;
                cid[sidx(idx)] = (short)l;
            }
        }
    }
    __syncthreads();

    // scatter: label of sorted position i goes to original index irow[i]
    short* glabRow = g_lab + (size_t)row * NN;
    for (int i = tid; i < NN; i += LTPB){
        glabRow[irow[i]] = cid[sidx(i)];
    }
    if (tid == 0) g_ncl[row] = (int)total;
}

// ---------------- output: offsets computed per-block + bitmap expansion ----
__global__ void __launch_bounds__(256) output_kernel(float* __restrict__ out){
    __shared__ short labT[DD][66];
    __shared__ int offs[DD];
    int b  = blockIdx.y;
    int n0 = blockIdx.x * 64;
    int tid = threadIdx.x, w = tid >> 5, lane = tid & 31;

    // per-block exclusive prefix over g_ncl (64 dims, trivial)
    int myv = 0;
    if (tid < DD){ myv = g_ncl[b*DD + tid]; offs[tid] = myv; }
    __syncthreads();
    #pragma unroll
    for (int o = 1; o < DD; o <<= 1){
        int t2 = 0;
        if (tid < DD && tid >= o) t2 = offs[tid - o];
        __syncthreads();
        if (tid < DD) offs[tid] += t2;
        __syncthreads();
    }
    if (tid < DD) offs[tid] -= myv;   // exclusive

    for (int l = tid; l < DD*64; l += 256){
        int d = l >> 6, i = l & 63;
        labT[d][i] = g_lab[((size_t)(b*DD + d))*NN + n0 + i];
    }
    __syncthreads();

    int q = lane >> 3;
    for (int i = w; i < 64; i += 8){
        int lb0 = labT[lane][i];
        int lb1 = labT[lane + 32][i];
        int g0 = -1, g1 = -1;
        if (lb0 >= 0){ int g = lb0 + offs[lane];      if (g < NCMAX) g0 = g; }
        if (lb1 >= 0){ int g = lb1 + offs[lane + 32]; if (g < NCMAX) g1 = g; }
        u32 myw[4];
        #pragma unroll
        for (int wi = 0; wi < 16; ++wi){
            u32 c = 0;
            if ((g0 >> 5) == wi) c |= 1u << (g0 & 31);
            if ((g1 >> 5) == wi) c |= 1u << (g1 & 31);
            u32 word = __reduce_or_sync(0xffffffffu, c);
            if (q == (wi & 3)) myw[wi >> 2] = word;
        }
        float4* op = reinterpret_cast<float4*>(out + ((size_t)(b*NN + n0 + i))*NCMAX);
        int sh = (lane & 7) * 4;
        #pragma unroll
        for (int k = 0; k < 4; ++k){
            u32 word = myw[k];
            float4 v;
            v.x = (word >> (sh + 0)) & 1u ? 1.0f : 0.0f;
            v.y = (word >> (sh + 1)) & 1u ? 1.0f : 0.0f;
            v.z = (word >> (sh + 2)) & 1u ? 1.0f : 0.0f;
            v.w = (word >> (sh + 3)) & 1u ? 1.0f : 0.0f;
            __stcs(op + k*32 + lane, v);
        }
    }
}

extern "C" void kernel_launch(void* const* d_in, const int* in_sizes, int n_in,
                              void* d_out, int out_size){
    const float* feat = (const float*)d_in[0];
    float* out = (float*)d_out;
    (void)in_sizes; (void)n_in; (void)out_size;

    int sortSmem = (int)sizeof(typename BlockSort::TempStorage);
    cudaFuncSetAttribute(sort_kernel,
                         cudaFuncAttributeMaxDynamicSharedMemorySize, sortSmem);
    cudaFuncSetAttribute(label_kernel,
                         cudaFuncAttributeMaxDynamicSharedMemorySize,
                         (int)sizeof(LSmem));

    transpose_kernel<<<dim3(NN/32, DD/32, BB), dim3(32, 32)>>>(feat);   // #1
    noop_kernel<<<1, 32>>>();                                           // #2
    noop_kernel<<<1, 32>>>();                                           // #3
    sort_kernel<<<NROWS, SBT, sortSmem>>>();                            // #4 (ncu slot)
    label_kernel<<<NROWS, LTPB, sizeof(LSmem)>>>();                     // #5
    output_kernel<<<dim3(NN/64, BB), 256>>>(out);                       // #6
}

// round 15
// speedup vs baseline: 1.1881x; 1.0111x over previous
#include <cuda_runtime.h>
#include <cstdint>
#include <cub/block/block_radix_sort.cuh>

typedef unsigned int u32;
typedef unsigned short u16;

#define BB 8
#define NN 16384
#define DD 64
#define NCMAX 512
#define EPSF 0.1f
#define NROWS (BB*DD)

#define SBT 512
#define SIPT 32

#define LTPB 512
#define LPT 32
#define LWARPS 16

__device__ float g_featT[(size_t)BB*DD*NN];   // (b, d, n) transposed features
__device__ u32   g_sorted[(size_t)BB*DD*NN];  // per-row sorted (monotone u32) keys
__device__ u16   g_sidx[(size_t)BB*DD*NN];    // original index per sorted position
__device__ short g_lab[(size_t)BB*DD*NN];     // per-point local labels
__device__ int   g_ncl[NROWS];

__device__ __forceinline__ u32 f2u(float f){
    u32 u = __float_as_uint(f);
    return (u & 0x80000000u) ? ~u : (u | 0x80000000u);
}
__device__ __forceinline__ float u2f(u32 u){
    u32 v = (u & 0x80000000u) ? (u & 0x7fffffffu) : ~u;
    return __uint_as_float(v);
}
__device__ __forceinline__ float posInf(){ return __int_as_float(0x7f800000); }
__device__ __forceinline__ float negInf(){ return __int_as_float((int)0xff800000); }

// XOR bank swizzle: bijective (high bits unchanged). With LPT=32 the
// per-thread pattern i=tid*32+e maps to bank = e ^ lane -> conflict-free.
__device__ __forceinline__ int sidx(int i){ return i ^ ((i >> 5) & 31); }

// ---------------- warp scans ----------------
__device__ __forceinline__ u32 warpInclAdd(u32 v){
    int lane = threadIdx.x & 31;
    #pragma unroll
    for (int o = 1; o < 32; o <<= 1){
        u32 t = __shfl_up_sync(0xffffffffu, v, o);
        if (lane >= o) v += t;
    }
    return v;
}
__device__ __forceinline__ int warpInclMax(int v){
    int lane = threadIdx.x & 31;
    #pragma unroll
    for (int o = 1; o < 32; o <<= 1){
        int t = __shfl_up_sync(0xffffffffu, v, o);
        if (lane >= o) v = max(v, t);
    }
    return v;
}
__device__ __forceinline__ int warpInclMin(int v){
    int lane = threadIdx.x & 31;
    #pragma unroll
    for (int o = 1; o < 32; o <<= 1){
        int t = __shfl_up_sync(0xffffffffu, v, o);
        if (lane >= o) v = min(v, t);
    }
    return v;
}

// ---------------- block scans (LTPB threads, all must call) ----------------
__device__ u32 blkExclAdd(u32 v, int* tmp, u32* total){
    int lane = threadIdx.x & 31, w = threadIdx.x >> 5;
    u32 inc = warpInclAdd(v);
    if (lane == 31) tmp[w] = (int)inc;
    __syncthreads();
    if (w == 0){
        u32 t = (lane < LWARPS) ? (u32)tmp[lane] : 0u;
        u32 ti = warpInclAdd(t);
        if (lane < LWARPS) tmp[lane] = (int)ti;
    }
    __syncthreads();
    u32 carry = (w > 0) ? (u32)tmp[w-1] : 0u;
    if (total) *total = (u32)tmp[LWARPS-1];
    u32 res = carry + inc - v;
    __syncthreads();
    return res;
}
__device__ int blkExclMax(int v, int* tmp){   // identity -1
    int lane = threadIdx.x & 31, w = threadIdx.x >> 5;
    int inc = warpInclMax(v);
    int ex = __shfl_up_sync(0xffffffffu, inc, 1);
    if (lane == 0) ex = -1;
    if (lane == 31) tmp[w] = inc;
    __syncthreads();
    if (w == 0){
        int t = (lane < LWARPS) ? tmp[lane] : -1;
        int ti = warpInclMax(t);
        if (lane < LWARPS) tmp[lane] = ti;
    }
    __syncthreads();
    int carry = (w > 0) ? tmp[w-1] : -1;
    int res = max(carry, ex);
    __syncthreads();
    return res;
}
__device__ int blkExclMin(int v, int* tmp){   // identity NN
    int lane = threadIdx.x & 31, w = threadIdx.x >> 5;
    int inc = warpInclMin(v);
    int ex = __shfl_up_sync(0xffffffffu, inc, 1);
    if (lane == 0) ex = NN;
    if (lane == 31) tmp[w] = inc;
    __syncthreads();
    if (w == 0){
        int t = (lane < LWARPS) ? tmp[lane] : NN;
        int ti = warpInclMin(t);
        if (lane < LWARPS) tmp[lane] = ti;
    }
    __syncthreads();
    int carry = (w > 0) ? tmp[w-1] : NN;
    int res = min(carry, ex);
    __syncthreads();
    return res;
}
// reverse exclusive min: for thread t, min over threads t' > t
__device__ int blkRevExclMin(int v, int* tmp, int* xch){
    int t = threadIdx.x;
    xch[(LTPB-1) - t] = v; __syncthreads();
    int rv = xch[t];        __syncthreads();
    int e = blkExclMin(rv, tmp);
    xch[t] = e;             __syncthreads();
    int r = xch[(LTPB-1) - t]; __syncthreads();
    return r;
}

// ---------------- no-op kernel (ncu slot aiming) ----------------
__global__ void noop_kernel(){}

// ---------------- transpose: (B,N,D) -> (B,D,N) ----------------
__global__ void transpose_kernel(const float* __restrict__ feat){
    __shared__ float tile[32][33];
    int b  = blockIdx.z;
    int d0 = blockIdx.y * 32;
    int n0 = blockIdx.x * 32;
    int tx = threadIdx.x, ty = threadIdx.y;
    tile[ty][tx] = feat[((size_t)b*NN + (n0+ty))*DD + (d0+tx)];
    __syncthreads();
    g_featT[((size_t)b*DD + (d0+ty))*NN + (n0+tx)] = tile[tx][ty];
}

// ---------------- sort: CUB pair radix sort, 512 thr x 32 items, 6-bit ----
// Proven optimum for this shape: 6-bit (R12) beats 7-bit (R14: bigger rank
// scans) and 1024x16 (R13: spills at the 64-reg cap).
typedef cub::BlockRadixSort<u32, SBT, SIPT, u16, 6> BlockSort;

__global__ void __launch_bounds__(SBT) sort_kernel(){
    extern __shared__ char smemRaw[];
    typename BlockSort::TempStorage* ts =
        reinterpret_cast<typename BlockSort::TempStorage*>(smemRaw);
    int row = blockIdx.x;
    const float* __restrict__ xrow = g_featT + (size_t)row * NN;
    int t = threadIdx.x;
    u32 keys[SIPT];
    u16 vals[SIPT];
    #pragma unroll
    for (int j = 0; j < SIPT; ++j){
        int src = j*SBT + t;            // striped load; pairing is what matters
        keys[j] = f2u(xrow[src]);
        vals[j] = (u16)src;
    }
    BlockSort(*ts).SortBlockedToStriped(keys, vals);
    u32* __restrict__ srow = g_sorted + (size_t)row * NN;
    u16* __restrict__ irow = g_sidx   + (size_t)row * NN;
    #pragma unroll
    for (int j = 0; j < SIPT; ++j){
        srow[j*SBT + t] = keys[j];
        irow[j*SBT + t] = vals[j];
    }
}

// ---------------- label kernel: one block per row, 2 CTAs/SM ---------------
struct LSmem {
    float xs[NN];        // sorted values, swizzled storage (64KB)
    short cidS[NN];      // cid / ni-temp / final labels, swizzled storage (32KB)
    int xch[LTPB];
    int tmp[LWARPS+1];
};

__global__ void __launch_bounds__(LTPB, 2) label_kernel(){
    extern __shared__ char smemRaw[];
    LSmem* S = reinterpret_cast<LSmem*>(smemRaw);
    int row = blockIdx.x;
    const u32* __restrict__ srow = g_sorted + (size_t)row * NN;
    const u16* __restrict__ irow = g_sidx   + (size_t)row * NN;
    int tid = threadIdx.x;

    // vectorized load: 4 keys per LDG.128
    float* xs = S->xs;
    {
        const uint4* __restrict__ srow4 = reinterpret_cast<const uint4*>(srow);
        for (int i = tid; i < NN/4; i += LTPB){
            uint4 k = srow4[i];
            int b4 = i * 4;
            xs[sidx(b4 + 0)] = u2f(k.x);
            xs[sidx(b4 + 1)] = u2f(k.y);
            xs[sidx(b4 + 2)] = u2f(k.z);
            xs[sidx(b4 + 3)] = u2f(k.w);
        }
    }
    __syncthreads();

    // bounds-checked sorted-value load (sentinels outside [0,NN))
    auto loadx = [&](int i) -> float {
        if (i < 0)   return negInf();
        if (i >= NN) return posInf();
        return xs[sidx(i)];
    };

    // ---- core test, O(1) per element via 9-point sliding window ----
    // core(i)  <=>  exists k in [0,4]: xs[i-k] >= x-eps  AND  xs[i+4-k] <= x+eps
    int p0 = tid * LPT;
    u32 coreMask = 0;
    {
        float v[9];
        #pragma unroll
        for (int j = 0; j < 9; ++j) v[j] = loadx(p0 - 4 + j);
        #pragma unroll
        for (int e = 0; e < LPT; ++e){
            float x = v[4];
            float a = x + EPSF, bnd = x - EPSF;
            bool core = false;
            #pragma unroll
            for (int k = 0; k <= 4; ++k)
                core |= (v[4 - k] >= bnd) && (v[8 - k] <= a);
            if (core) coreMask |= (1u << e);
            #pragma unroll
            for (int j = 0; j < 8; ++j) v[j] = v[j + 1];
            v[8] = loadx(p0 + e + 5);
        }
    }

    // per-thread summaries
    int localPrev = -1, localNext = NN;
    #pragma unroll
    for (int e = 0; e < LPT; ++e) if (coreMask & (1u << e)) localPrev = p0 + e;
    #pragma unroll
    for (int e = LPT-1; e >= 0; --e) if (coreMask & (1u << e)) localNext = p0 + e;

    int carryP = blkExclMax(localPrev, S->tmp);
    int carryN = blkRevExclMin(localNext, S->tmp, S->xch);

    // new-cluster flags + local count
    u32 ncMask = 0;
    {
        int runP = carryP;
        #pragma unroll
        for (int e = 0; e < LPT; ++e){
            if (coreMask & (1u << e)){
                float x = xs[sidx(p0 + e)];
                float pv = (runP >= 0) ? xs[sidx(runP)] : negInf();
                if (x - pv > EPSF) ncMask |= (1u << e);
                runP = p0 + e;
            }
        }
    }
    u32 total = 0;
    u32 carryC = blkExclAdd((u32)__popc(ncMask), S->tmp, &total);

    // cid per sorted position (swizzled short layout)
    short* cid = S->cidS;
    {
        int c = (int)carryC;
        #pragma unroll
        for (int e = 0; e < LPT; ++e){
            if (ncMask & (1u << e)) ++c;
            cid[sidx(p0 + e)] = (short)(c - 1);
        }
    }
    __syncthreads();

    // labels in place: reverse pass stashes next-core index in BORDER slots;
    // forward pass reads cross-thread data only from CORE slots.
    {
        int rN = carryN;
        #pragma unroll
        for (int e = LPT-1; e >= 0; --e){
            int idx = p0 + e;
            if (coreMask & (1u << e)) rN = idx;
            else cid[sidx(idx)] = (short)rN;
        }
        int rP = carryP;
        #pragma unroll
        for (int e = 0; e < LPT; ++e){
            int idx = p0 + e;
            if (coreMask & (1u << e)){
                rP = idx;
            } else {
                int ni = cid[sidx(idx)];
                float x = xs[sidx(idx)];
                float lv = (rP >= 0) ? xs[sidx(rP)]  : negInf();
                float rv = (ni < NN) ? xs[sidx(ni)]  : posInf();
                float dl = x - lv, dr = rv - x;
                int lc = (rP >= 0) ? cid[sidx(rP)] : -1;
                int rc = (ni < NN) ? cid[sidx(ni)] : -1;
                int bc = (dl <= dr) ? lc : rc;
                int l = (fminf(dl, dr) <= EPSF) ? bc : -1;
                cid[sidx(idx)] = (short)l;
            }
        }
    }
    __syncthreads();

    // scatter: label of sorted position i goes to original index irow[i]
    // vectorized index read: 4 u16 per LDG.64
    short* glabRow = g_lab + (size_t)row * NN;
    {
        const ushort4* __restrict__ irow4 = reinterpret_cast<const ushort4*>(irow);
        for (int i = tid; i < NN/4; i += LTPB){
            ushort4 ix = irow4[i];
            int b4 = i * 4;
            glabRow[ix.x] = cid[sidx(b4 + 0)];
            glabRow[ix.y] = cid[sidx(b4 + 1)];
            glabRow[ix.z] = cid[sidx(b4 + 2)];
            glabRow[ix.w] = cid[sidx(b4 + 3)];
        }
    }
    if (tid == 0) g_ncl[row] = (int)total;
}

// ---------------- output: offsets computed per-block + bitmap expansion ----
__global__ void __launch_bounds__(256) output_kernel(float* __restrict__ out){
    __shared__ short labT[DD][66];
    __shared__ int offs[DD];
    int b  = blockIdx.y;
    int n0 = blockIdx.x * 64;
    int tid = threadIdx.x, w = tid >> 5, lane = tid & 31;

    // per-block exclusive prefix over g_ncl (64 dims, trivial)
    int myv = 0;
    if (tid < DD){ myv = g_ncl[b*DD + tid]; offs[tid] = myv; }
    __syncthreads();
    #pragma unroll
    for (int o = 1; o < DD; o <<= 1){
        int t2 = 0;
        if (tid < DD && tid >= o) t2 = offs[tid - o];
        __syncthreads();
        if (tid < DD) offs[tid] += t2;
        __syncthreads();
    }
    if (tid < DD) offs[tid] -= myv;   // exclusive

    for (int l = tid; l < DD*64; l += 256){
        int d = l >> 6, i = l & 63;
        labT[d][i] = g_lab[((size_t)(b*DD + d))*NN + n0 + i];
    }
    __syncthreads();

    int q = lane >> 3;
    for (int i = w; i < 64; i += 8){
        int lb0 = labT[lane][i];
        int lb1 = labT[lane + 32][i];
        int g0 = -1, g1 = -1;
        if (lb0 >= 0){ int g = lb0 + offs[lane];      if (g < NCMAX) g0 = g; }
        if (lb1 >= 0){ int g = lb1 + offs[lane + 32]; if (g < NCMAX) g1 = g; }
        u32 myw[4];
        #pragma unroll
        for (int wi = 0; wi < 16; ++wi){
            u32 c = 0;
            if ((g0 >> 5) == wi) c |= 1u << (g0 & 31);
            if ((g1 >> 5) == wi) c |= 1u << (g1 & 31);
            u32 word = __reduce_or_sync(0xffffffffu, c);
            if (q == (wi & 3)) myw[wi >> 2] = word;
        }
        float4* op = reinterpret_cast<float4*>(out + ((size_t)(b*NN + n0 + i))*NCMAX);
        int sh = (lane & 7) * 4;
        #pragma unroll
        for (int k = 0; k < 4; ++k){
            u32 word = myw[k];
            float4 v;
            v.x = (word >> (sh + 0)) & 1u ? 1.0f : 0.0f;
            v.y = (word >> (sh + 1)) & 1u ? 1.0f : 0.0f;
            v.z = (word >> (sh + 2)) & 1u ? 1.0f : 0.0f;
            v.w = (word >> (sh + 3)) & 1u ? 1.0f : 0.0f;
            __stcs(op + k*32 + lane, v);
        }
    }
}

extern "C" void kernel_launch(void* const* d_in, const int* in_sizes, int n_in,
                              void* d_out, int out_size){
    const float* feat = (const float*)d_in[0];
    float* out = (float*)d_out;
    (void)in_sizes; (void)n_in; (void)out_size;

    int sortSmem = (int)sizeof(typename BlockSort::TempStorage);
    cudaFuncSetAttribute(sort_kernel,
                         cudaFuncAttributeMaxDynamicSharedMemorySize, sortSmem);
    cudaFuncSetAttribute(label_kernel,
                         cudaFuncAttributeMaxDynamicSharedMemorySize,
                         (int)sizeof(LSmem));

    transpose_kernel<<<dim3(NN/32, DD/32, BB), dim3(32, 32)>>>(feat);   // #1
    sort_kernel<<<NROWS, SBT, sortSmem>>>();                            // #2
    noop_kernel<<<1, 32>>>();                                           // #3
    label_kernel<<<NROWS, LTPB, sizeof(LSmem)>>>();                     // #4 (ncu slot)
    output_kernel<<<dim3(NN/64, BB), 256>>>(out);                       // #5
}

// round 16
// speedup vs baseline: 1.4050x; 1.1825x over previous
#include <cuda_runtime.h>
#include <cstdint>
#include <cub/block/block_radix_sort.cuh>

typedef unsigned int u32;
typedef unsigned short u16;

#define BB 8
#define NN 16384
#define DD 64
#define NCMAX 512
#define EPSF 0.1f
#define NROWS (BB*DD)

#define SBT 512
#define SIPT 32

#define LTPB 512
#define LPT 32
#define LWARPS 16

__device__ float g_featT[(size_t)BB*DD*NN];   // (b, d, n) transposed features
__device__ u32   g_sorted[(size_t)BB*DD*NN];  // per-row sorted (monotone u32) keys
__device__ short g_lab[(size_t)BB*DD*NN];     // per-point local labels
__device__ int   g_ncl[NROWS];

__device__ __forceinline__ u32 f2u(float f){
    u32 u = __float_as_uint(f);
    return (u & 0x80000000u) ? ~u : (u | 0x80000000u);
}
__device__ __forceinline__ float u2f(u32 u){
    u32 v = (u & 0x80000000u) ? (u & 0x7fffffffu) : ~u;
    return __uint_as_float(v);
}
__device__ __forceinline__ float posInf(){ return __int_as_float(0x7f800000); }
__device__ __forceinline__ float negInf(){ return __int_as_float((int)0xff800000); }

// XOR bank swizzle: bijective (high bits unchanged). With LPT=32 the
// per-thread pattern i=tid*32+e maps to bank = e ^ lane -> conflict-free.
__device__ __forceinline__ int sidx(int i){ return i ^ ((i >> 5) & 31); }

// ---------------- warp scans ----------------
__device__ __forceinline__ u32 warpInclAdd(u32 v){
    int lane = threadIdx.x & 31;
    #pragma unroll
    for (int o = 1; o < 32; o <<= 1){
        u32 t = __shfl_up_sync(0xffffffffu, v, o);
        if (lane >= o) v += t;
    }
    return v;
}
__device__ __forceinline__ int warpInclMax(int v){
    int lane = threadIdx.x & 31;
    #pragma unroll
    for (int o = 1; o < 32; o <<= 1){
        int t = __shfl_up_sync(0xffffffffu, v, o);
        if (lane >= o) v = max(v, t);
    }
    return v;
}
__device__ __forceinline__ int warpInclMin(int v){
    int lane = threadIdx.x & 31;
    #pragma unroll
    for (int o = 1; o < 32; o <<= 1){
        int t = __shfl_up_sync(0xffffffffu, v, o);
        if (lane >= o) v = min(v, t);
    }
    return v;
}

// ---------------- block scans (LTPB threads, all must call) ----------------
__device__ u32 blkExclAdd(u32 v, int* tmp, u32* total){
    int lane = threadIdx.x & 31, w = threadIdx.x >> 5;
    u32 inc = warpInclAdd(v);
    if (lane == 31) tmp[w] = (int)inc;
    __syncthreads();
    if (w == 0){
        u32 t = (lane < LWARPS) ? (u32)tmp[lane] : 0u;
        u32 ti = warpInclAdd(t);
        if (lane < LWARPS) tmp[lane] = (int)ti;
    }
    __syncthreads();
    u32 carry = (w > 0) ? (u32)tmp[w-1] : 0u;
    if (total) *total = (u32)tmp[LWARPS-1];
    u32 res = carry + inc - v;
    __syncthreads();
    return res;
}
__device__ int blkExclMax(int v, int* tmp){   // identity -1
    int lane = threadIdx.x & 31, w = threadIdx.x >> 5;
    int inc = warpInclMax(v);
    int ex = __shfl_up_sync(0xffffffffu, inc, 1);
    if (lane == 0) ex = -1;
    if (lane == 31) tmp[w] = inc;
    __syncthreads();
    if (w == 0){
        int t = (lane < LWARPS) ? tmp[lane] : -1;
        int ti = warpInclMax(t);
        if (lane < LWARPS) tmp[lane] = ti;
    }
    __syncthreads();
    int carry = (w > 0) ? tmp[w-1] : -1;
    int res = max(carry, ex);
    __syncthreads();
    return res;
}
__device__ int blkExclMin(int v, int* tmp){   // identity NN
    int lane = threadIdx.x & 31, w = threadIdx.x >> 5;
    int inc = warpInclMin(v);
    int ex = __shfl_up_sync(0xffffffffu, inc, 1);
    if (lane == 0) ex = NN;
    if (lane == 31) tmp[w] = inc;
    __syncthreads();
    if (w == 0){
        int t = (lane < LWARPS) ? tmp[lane] : NN;
        int ti = warpInclMin(t);
        if (lane < LWARPS) tmp[lane] = ti;
    }
    __syncthreads();
    int carry = (w > 0) ? tmp[w-1] : NN;
    int res = min(carry, ex);
    __syncthreads();
    return res;
}
// reverse exclusive min: for thread t, min over threads t' > t
__device__ int blkRevExclMin(int v, int* tmp, int* xch){
    int t = threadIdx.x;
    xch[(LTPB-1) - t] = v; __syncthreads();
    int rv = xch[t];        __syncthreads();
    int e = blkExclMin(rv, tmp);
    xch[t] = e;             __syncthreads();
    int r = xch[(LTPB-1) - t]; __syncthreads();
    return r;
}

// ---------------- no-op kernel (ncu slot aiming) ----------------
__global__ void noop_kernel(){}

// ---------------- transpose: (B,N,D) -> (B,D,N) ----------------
__global__ void transpose_kernel(const float* __restrict__ feat){
    __shared__ float tile[32][33];
    int b  = blockIdx.z;
    int d0 = blockIdx.y * 32;
    int n0 = blockIdx.x * 32;
    int tx = threadIdx.x, ty = threadIdx.y;
    tile[ty][tx] = feat[((size_t)b*NN + (n0+ty))*DD + (d0+tx)];
    __syncthreads();
    g_featT[((size_t)b*DD + (d0+ty))*NN + (n0+tx)] = tile[tx][ty];
}

// ---------------- sort: CUB keys-only radix sort (R7 config: 115us) -------
typedef cub::BlockRadixSort<u32, SBT, SIPT, cub::NullType, 6> BlockSort;

__global__ void __launch_bounds__(SBT) sort_kernel(){
    extern __shared__ char smemRaw[];
    typename BlockSort::TempStorage* ts =
        reinterpret_cast<typename BlockSort::TempStorage*>(smemRaw);
    int row = blockIdx.x;
    const float* __restrict__ xrow = g_featT + (size_t)row * NN;
    int t = threadIdx.x;
    u32 keys[SIPT];
    #pragma unroll
    for (int j = 0; j < SIPT; ++j)
        keys[j] = f2u(xrow[j*SBT + t]);
    BlockSort(*ts).SortBlockedToStriped(keys);
    u32* __restrict__ srow = g_sorted + (size_t)row * NN;
    #pragma unroll
    for (int j = 0; j < SIPT; ++j)
        srow[j*SBT + t] = keys[j];
}

// ---------------- label kernel: one block per row, 2 CTAs/SM ---------------
struct LSmem {
    float xs[NN];        // sorted values, swizzled storage (64KB)
    short cidS[NN];      // cid / ni-temp / final labels, swizzled storage (32KB)
    int xch[LTPB];
    int tmp[LWARPS+1];
};

__global__ void __launch_bounds__(LTPB, 2) label_kernel(){
    extern __shared__ char smemRaw[];
    LSmem* S = reinterpret_cast<LSmem*>(smemRaw);
    int row = blockIdx.x;
    const u32* __restrict__ srow = g_sorted + (size_t)row * NN;
    const float* __restrict__ xrow = g_featT + (size_t)row * NN;
    int tid = threadIdx.x;

    // vectorized load: 4 keys per LDG.128
    float* xs = S->xs;
    {
        const uint4* __restrict__ srow4 = reinterpret_cast<const uint4*>(srow);
        for (int i = tid; i < NN/4; i += LTPB){
            uint4 k = srow4[i];
            int b4 = i * 4;
            xs[sidx(b4 + 0)] = u2f(k.x);
            xs[sidx(b4 + 1)] = u2f(k.y);
            xs[sidx(b4 + 2)] = u2f(k.z);
            xs[sidx(b4 + 3)] = u2f(k.w);
        }
    }
    __syncthreads();

    // bounds-checked sorted-value load (sentinels outside [0,NN))
    auto loadx = [&](int i) -> float {
        if (i < 0)   return negInf();
        if (i >= NN) return posInf();
        return xs[sidx(i)];
    };

    // ---- core test, O(1) per element via 9-point sliding window ----
    // core(i)  <=>  exists k in [0,4]: xs[i-k] >= x-eps  AND  xs[i+4-k] <= x+eps
    int p0 = tid * LPT;
    u32 coreMask = 0;
    {
        float v[9];
        #pragma unroll
        for (int j = 0; j < 9; ++j) v[j] = loadx(p0 - 4 + j);
        #pragma unroll
        for (int e = 0; e < LPT; ++e){
            float x = v[4];
            float a = x + EPSF, bnd = x - EPSF;
            bool core = false;
            #pragma unroll
            for (int k = 0; k <= 4; ++k)
                core |= (v[4 - k] >= bnd) && (v[8 - k] <= a);
            if (core) coreMask |= (1u << e);
            #pragma unroll
            for (int j = 0; j < 8; ++j) v[j] = v[j + 1];
            v[8] = loadx(p0 + e + 5);
        }
    }

    // per-thread summaries
    int localPrev = -1, localNext = NN;
    #pragma unroll
    for (int e = 0; e < LPT; ++e) if (coreMask & (1u << e)) localPrev = p0 + e;
    #pragma unroll
    for (int e = LPT-1; e >= 0; --e) if (coreMask & (1u << e)) localNext = p0 + e;

    int carryP = blkExclMax(localPrev, S->tmp);
    int carryN = blkRevExclMin(localNext, S->tmp, S->xch);

    // new-cluster flags + local count
    u32 ncMask = 0;
    {
        int runP = carryP;
        #pragma unroll
        for (int e = 0; e < LPT; ++e){
            if (coreMask & (1u << e)){
                float x = xs[sidx(p0 + e)];
                float pv = (runP >= 0) ? xs[sidx(runP)] : negInf();
                if (x - pv > EPSF) ncMask |= (1u << e);
                runP = p0 + e;
            }
        }
    }
    u32 total = 0;
    u32 carryC = blkExclAdd((u32)__popc(ncMask), S->tmp, &total);

    // cid per sorted position (swizzled short layout)
    short* cid = S->cidS;
    {
        int c = (int)carryC;
        #pragma unroll
        for (int e = 0; e < LPT; ++e){
            if (ncMask & (1u << e)) ++c;
            cid[sidx(p0 + e)] = (short)(c - 1);
        }
    }
    __syncthreads();

    // labels in place: reverse pass stashes next-core index in BORDER slots;
    // forward pass reads cross-thread data only from CORE slots.
    {
        int rN = carryN;
        #pragma unroll
        for (int e = LPT-1; e >= 0; --e){
            int idx = p0 + e;
            if (coreMask & (1u << e)) rN = idx;
            else cid[sidx(idx)] = (short)rN;
        }
        int rP = carryP;
        #pragma unroll
        for (int e = 0; e < LPT; ++e){
            int idx = p0 + e;
            if (coreMask & (1u << e)){
                rP = idx;
            } else {
                int ni = cid[sidx(idx)];
                float x = xs[sidx(idx)];
                float lv = (rP >= 0) ? xs[sidx(rP)]  : negInf();
                float rv = (ni < NN) ? xs[sidx(ni)]  : posInf();
                float dl = x - lv, dr = rv - x;
                int lc = (rP >= 0) ? cid[sidx(rP)] : -1;
                int rc = (ni < NN) ? cid[sidx(ni)] : -1;
                int bc = (dl <= dr) ? lc : rc;
                int l = (fminf(dl, dr) <= EPSF) ? bc : -1;
                cid[sidx(idx)] = (short)l;
            }
        }
    }
    __syncthreads();

    // lookup: branchless 14-level lower_bound (NN = 2^14), 4-way ILP.
    // x is bit-exactly present in xs (f2u/u2f bijective), so lower_bound
    // lands on an equal-valued position; equal values have equal labels.
    short* glabRow = g_lab + (size_t)row * NN;
    #pragma unroll 1
    for (int it = 0; it < NN/(LTPB*4); ++it){
        int i = tid + it*(LTPB*4);
        float x0 = xrow[i];
        float x1 = xrow[i +   LTPB];
        float x2 = xrow[i + 2*LTPB];
        float x3 = xrow[i + 3*LTPB];
        int q0 = 0, q1 = 0, q2 = 0, q3 = 0;
        #pragma unroll
        for (int h = NN/2; h > 0; h >>= 1){
            q0 += (xs[sidx(q0 + h - 1)] < x0) ? h : 0;
            q1 += (xs[sidx(q1 + h - 1)] < x1) ? h : 0;
            q2 += (xs[sidx(q2 + h - 1)] < x2) ? h : 0;
            q3 += (xs[sidx(q3 + h - 1)] < x3) ? h : 0;
        }
        glabRow[i]          = cid[sidx(q0)];
        glabRow[i +   LTPB] = cid[sidx(q1)];
        glabRow[i + 2*LTPB] = cid[sidx(q2)];
        glabRow[i + 3*LTPB] = cid[sidx(q3)];
    }
    if (tid == 0) g_ncl[row] = (int)total;
}

// ---------------- output: offsets computed per-block + bitmap expansion ----
__global__ void __launch_bounds__(256) output_kernel(float* __restrict__ out){
    __shared__ short labT[DD][66];
    __shared__ int offs[DD];
    int b  = blockIdx.y;
    int n0 = blockIdx.x * 64;
    int tid = threadIdx.x, w = tid >> 5, lane = tid & 31;

    // per-block exclusive prefix over g_ncl (64 dims, trivial)
    int myv = 0;
    if (tid < DD){ myv = g_ncl[b*DD + tid]; offs[tid] = myv; }
    __syncthreads();
    #pragma unroll
    for (int o = 1; o < DD; o <<= 1){
        int t2 = 0;
        if (tid < DD && tid >= o) t2 = offs[tid - o];
        __syncthreads();
        if (tid < DD) offs[tid] += t2;
        __syncthreads();
    }
    if (tid < DD) offs[tid] -= myv;   // exclusive

    for (int l = tid; l < DD*64; l += 256){
        int d = l >> 6, i = l & 63;
        labT[d][i] = g_lab[((size_t)(b*DD + d))*NN + n0 + i];
    }
    __syncthreads();

    int q = lane >> 3;
    for (int i = w; i < 64; i += 8){
        int lb0 = labT[lane][i];
        int lb1 = labT[lane + 32][i];
        int g0 = -1, g1 = -1;
        if (lb0 >= 0){ int g = lb0 + offs[lane];      if (g < NCMAX) g0 = g; }
        if (lb1 >= 0){ int g = lb1 + offs[lane + 32]; if (g < NCMAX) g1 = g; }
        u32 myw[4];
        #pragma unroll
        for (int wi = 0; wi < 16; ++wi){
            u32 c = 0;
            if ((g0 >> 5) == wi) c |= 1u << (g0 & 31);
            if ((g1 >> 5) == wi) c |= 1u << (g1 & 31);
            u32 word = __reduce_or_sync(0xffffffffu, c);
            if (q == (wi & 3)) myw[wi >> 2] = word;
        }
        float4* op = reinterpret_cast<float4*>(out + ((size_t)(b*NN + n0 + i))*NCMAX);
        int sh = (lane & 7) * 4;
        #pragma unroll
        for (int k = 0; k < 4; ++k){
            u32 word = myw[k];
            float4 v;
            v.x = (word >> (sh + 0)) & 1u ? 1.0f : 0.0f;
            v.y = (word >> (sh + 1)) & 1u ? 1.0f : 0.0f;
            v.z = (word >> (sh + 2)) & 1u ? 1.0f : 0.0f;
            v.w = (word >> (sh + 3)) & 1u ? 1.0f : 0.0f;
            __stcs(op + k*32 + lane, v);
        }
    }
}

extern "C" void kernel_launch(void* const* d_in, const int* in_sizes, int n_in,
                              void* d_out, int out_size){
    const float* feat = (const float*)d_in[0];
    float* out = (float*)d_out;
    (void)in_sizes; (void)n_in; (void)out_size;

    int sortSmem = (int)sizeof(typename BlockSort::TempStorage);
    cudaFuncSetAttribute(sort_kernel,
                         cudaFuncAttributeMaxDynamicSharedMemorySize, sortSmem);
    cudaFuncSetAttribute(label_kernel,
                         cudaFuncAttributeMaxDynamicSharedMemorySize,
                         (int)sizeof(LSmem));

    transpose_kernel<<<dim3(NN/32, DD/32, BB), dim3(32, 32)>>>(feat);   // #1
    sort_kernel<<<NROWS, SBT, sortSmem>>>();                            // #2
    noop_kernel<<<1, 32>>>();                                           // #3
    label_kernel<<<NROWS, LTPB, sizeof(LSmem)>>>();                     // #4 (ncu slot)
    output_kernel<<<dim3(NN/64, BB), 256>>>(out);                       // #5
}